// round 9
// baseline (speedup 1.0000x reference)
#include <cuda_runtime.h>
#include <cuda_fp16.h>

#define SEQ    256
#define VOC    96
#define DEND   (SEQ * VOC)           // 24576 dendrites
#define ZROW   DEND                  // masked-position row (all QZ codes)
#define NWARP  16
#define WPOS   (SEQ / NWARP)         // 16 positions per warp

// log_w range: [log(2*sig(-1)), log(2*sig(1))] = [-0.620115, 0.379885], width 1.0
#define QS    0.0039370079f          // 1/254
#define QINV  254.0f
#define QM    (-0.1201145f)          // range midpoint
#define EPSZ  0.0019327f             // residual of masked-row code (QZ=31)

// int8 quantized transposed table: g_q[d*96+v] = quant(log(2*sigmoid(raw[v][d])))
__device__ __align__(128) signed char g_q[(DEND + 1) * VOC + 128];

// ---------------------------------------------------------------------------
// Kernel A: sigmoid/log + quantize + transpose. grid (768,3), block (32,8).
// ---------------------------------------------------------------------------
__global__ void prep_kernel(const float* __restrict__ raw) {
    __shared__ float tile[32][33];      // tile[v_local][d_local]
    const int d0 = blockIdx.x * 32;
    const int v0 = blockIdx.y * 32;
    const int tx = threadIdx.x, ty = threadIdx.y;

    #pragma unroll
    for (int i = ty; i < 32; i += 8) {
        const float x = raw[(v0 + i) * DEND + (d0 + tx)];
        tile[i][tx] = 0.69314718f - __logf(1.0f + __expf(-x));
    }
    __syncthreads();

    const int t  = ty * 32 + tx;        // 0..255
    const int dl = t >> 3;              // d_local 0..31
    const int vq = t & 7;               // which char4 of 32 v's

    char4 c;
    #pragma unroll
    for (int k = 0; k < 4; k++) {
        const float lw = tile[4 * vq + k][dl];
        int qi = __float2int_rn((lw - QM) * QINV);
        qi = max(-127, min(127, qi));
        ((char*)&c)[k] = (signed char)qi;
    }
    *(char4*)(g_q + (d0 + dl) * VOC + v0 + 4 * vq) = c;

    if (blockIdx.x == 0 && blockIdx.y == 0 && t < VOC / 4) {
        ((int*)(g_q + ZROW * VOC))[t] = 0x1F1F1F1F;   // QZ=31 per byte
    }
}

// dp4a byte extraction of one 32-bit word (4 vocab entries) into acc[o..o+3]
#define ACC4(W, o) do {                                                 \
    const int _w = (int)(W);                                            \
    acc[(o) + 0] = __dp4a(_w, (int)0x00000001, acc[(o) + 0]);           \
    acc[(o) + 1] = __dp4a(_w, (int)0x00000100, acc[(o) + 1]);           \
    acc[(o) + 2] = __dp4a(_w, (int)0x00010000, acc[(o) + 2]);           \
    acc[(o) + 3] = __dp4a(_w, (int)0x01000000, acc[(o) + 3]);           \
} while (0)

#define ACCUM(X) do {                                                   \
    ACC4((X).x, 0); ACC4((X).y, 4); ACC4((X).z, 8); ACC4((X).w, 12);    \
} while (0)

// ---------------------------------------------------------------------------
// Kernel B: one sample per block, 512 threads (16 warps).
// Warp w owns 16 positions; ONE LDG.128 fetches FOUR 96B rows:
// lane al<24 -> (rgrp=al/6, vgrp=al%6), 16B = 16 vocab of row s0+4i+rgrp.
// 4 LDG.128 per thread (depth-2 staging), 64 dp4a into 16 exact int32 accs.
// ---------------------------------------------------------------------------
__global__ void __launch_bounds__(32 * NWARP)
gather_kernel(const int* __restrict__ chars,
              float* __restrict__ out) {
    __shared__ int offs[SEQ];                     // byte offsets of rows
    __shared__ int cnt8[8];                       // per-warp active counts
    __shared__ int part[NWARP][24][16];           // 24 KB int partials

    const int b    = blockIdx.x;
    const int t    = threadIdx.x;                 // 0..511
    const int lane = t & 31;
    const int w    = t >> 5;
    const int s0   = w * WPOS;
    const int al   = (lane < 24) ? lane : lane - 8;   // dup lanes share lines
    const int rgrp = al / 6;                      // which of 4 rows
    const int vgrp = al - 6 * rgrp;               // which 16B chunk (16 vocab)
    const signed char* __restrict__ bp = g_q;

    if (t < SEQ) {
        const int c = chars[b * SEQ + t];
        const bool act = (c > 0);
        offs[t] = (act ? (t * VOC + c - 1) : ZROW) * VOC;
        const unsigned m = __ballot_sync(0xffffffffu, act);
        if (lane == 0) cnt8[w] = __popc(m);
    }
    __syncthreads();

    int acc[16];
    #pragma unroll
    for (int k = 0; k < 16; k++) acc[k] = 0;

    // Depth-2 staged gather: 4 LDG.128 per thread, consumers trail by 2.
    const int vb = vgrp * 16;
    const uint4 x0 = *(const uint4*)(bp + offs[s0      + rgrp] + vb);
    const uint4 x1 = *(const uint4*)(bp + offs[s0 +  4 + rgrp] + vb);
    const uint4 x2 = *(const uint4*)(bp + offs[s0 +  8 + rgrp] + vb);
    ACCUM(x0);
    const uint4 x3 = *(const uint4*)(bp + offs[s0 + 12 + rgrp] + vb);
    ACCUM(x1);
    ACCUM(x2);
    ACCUM(x3);

    if (lane < 24) {
        int4* dst = (int4*)&part[w][al][0];
        dst[0] = make_int4(acc[ 0], acc[ 1], acc[ 2], acc[ 3]);
        dst[1] = make_int4(acc[ 4], acc[ 5], acc[ 6], acc[ 7]);
        dst[2] = make_int4(acc[ 8], acc[ 9], acc[10], acc[11]);
        dst[3] = make_int4(acc[12], acc[13], acc[14], acc[15]);
    }
    __syncthreads();

    // Final reduce: thread v<96 sums its vocab entry over 16 warps x 4 rgrps.
    if (t < VOC) {
        const int vg  = t >> 4;                   // 0..5
        const int rem = t & 15;                   // acc index within lane
        int s = 0;
        #pragma unroll
        for (int k = 0; k < NWARP; k++) {
            #pragma unroll
            for (int r = 0; r < 4; r++)
                s += part[k][6 * r + vg][rem];
        }
        int nact = 0;
        #pragma unroll
        for (int k = 0; k < 8; k++) nact += cnt8[k];
        const float inv  = __frcp_rn((float)max(nact, 1));
        const float corr = 256.0f * QM - (float)(SEQ - nact) * EPSZ;
        out[b * VOC + t] = __expf((QS * (float)s + corr) * inv);
    }
}

// ---------------------------------------------------------------------------
extern "C" void kernel_launch(void* const* d_in, const int* in_sizes, int n_in,
                              void* d_out, int out_size) {
    const int*   chars = (const int*)d_in[0];     // (B, 256) int32
    const float* raw   = (const float*)d_in[1];   // (96, 24576) float32
    float*       out   = (float*)d_out;           // (B, 96) float32

    const int batch = in_sizes[0] / SEQ;

    dim3 pgrid(DEND / 32, VOC / 32);              // (768, 3)
    dim3 pblk(32, 8);
    prep_kernel<<<pgrid, pblk>>>(raw);

    gather_kernel<<<batch, 32 * NWARP>>>(chars, out);
}

// round 10
// speedup vs baseline: 1.0155x; 1.0155x over previous
#include <cuda_runtime.h>
#include <cuda_fp16.h>

#define SEQ    256
#define VOC    96
#define VPAD   128                   // padded int8 row: 128 B = 1 cache line
#define DEND   (SEQ * VOC)           // 24576 dendrites
#define ZROW   DEND                  // masked-position row (QZ codes)
#define NWARP  16
#define WPOS   (SEQ / NWARP)         // 16 positions per warp

// log_w range: [log(2*sig(-1)), log(2*sig(1))] = [-0.620115, 0.379885], width 1.0
#define QS    0.0039370079f          // 1/254
#define QINV  254.0f
#define QM    (-0.1201145f)          // range midpoint
#define EPSZ  0.0019327f             // residual of masked-row code (QZ=31)

// int8 quantized transposed table, rows padded/aligned to 128B. 3.1 MB.
__device__ __align__(128) signed char g_q[(DEND + 1) * VPAD];

// ---------------------------------------------------------------------------
// Kernel A: sigmoid/log + quantize + transpose into 128B rows.
// grid (768,3), block (32,8). y==2 tile also zeroes pad columns 96..127.
// ---------------------------------------------------------------------------
__global__ void prep_kernel(const float* __restrict__ raw) {
    __shared__ float tile[32][33];      // tile[v_local][d_local]
    const int d0 = blockIdx.x * 32;
    const int v0 = blockIdx.y * 32;
    const int tx = threadIdx.x, ty = threadIdx.y;

    #pragma unroll
    for (int i = ty; i < 32; i += 8) {
        const float x = raw[(v0 + i) * DEND + (d0 + tx)];
        tile[i][tx] = 0.69314718f - __logf(1.0f + __expf(-x));
    }
    __syncthreads();

    const int t  = ty * 32 + tx;        // 0..255
    const int dl = t >> 3;              // d_local 0..31
    const int vq = t & 7;               // which char4 of 32 v's

    char4 c;
    #pragma unroll
    for (int k = 0; k < 4; k++) {
        const float lw = tile[4 * vq + k][dl];
        int qi = __float2int_rn((lw - QM) * QINV);
        qi = max(-127, min(127, qi));
        ((char*)&c)[k] = (signed char)qi;
    }
    *(char4*)(g_q + (d0 + dl) * VPAD + v0 + 4 * vq) = c;

    if (blockIdx.y == 2) {              // zero pad columns 96..127
        const char4 z = make_char4(0, 0, 0, 0);
        *(char4*)(g_q + (d0 + dl) * VPAD + 96 + 4 * vq) = z;
    }
    if (blockIdx.x == 0 && blockIdx.y == 0 && t < VPAD / 4) {
        ((int*)(g_q + ZROW * VPAD))[t] = (t < 24) ? 0x1F1F1F1F : 0;
    }
}

// dp4a byte extraction of one 32-bit word (4 vocab entries) into acc[o..o+3]
#define ACC4(W, o) do {                                                 \
    const int _w = (int)(W);                                            \
    acc[(o) + 0] = __dp4a(_w, (int)0x00000001, acc[(o) + 0]);           \
    acc[(o) + 1] = __dp4a(_w, (int)0x00000100, acc[(o) + 1]);           \
    acc[(o) + 2] = __dp4a(_w, (int)0x00010000, acc[(o) + 2]);           \
    acc[(o) + 3] = __dp4a(_w, (int)0x01000000, acc[(o) + 3]);           \
} while (0)

#define ACCUM(X) do {                                                   \
    ACC4((X).x, 0); ACC4((X).y, 4); ACC4((X).z, 8); ACC4((X).w, 12);    \
} while (0)

// ---------------------------------------------------------------------------
// Kernel B: one sample per block, 512 threads (16 warps).
// ONE LDG.128 fetches FOUR 128B-aligned rows: lane -> (rgrp=lane>>3,
// vgrp=lane&7); each 8-lane group covers exactly one line (1 request/row,
// 4 wavefronts/instr -- the HW minimum). __ldcg bypasses L1 (table >> L1).
// ---------------------------------------------------------------------------
__global__ void __launch_bounds__(32 * NWARP)
gather_kernel(const int* __restrict__ chars,
              float* __restrict__ out) {
    __shared__ int offs[SEQ];                     // byte offsets of rows
    __shared__ int cnt8[8];                       // per-warp active counts
    __shared__ int part[NWARP][4][6][16];         // 24 KB int partials

    const int b    = blockIdx.x;
    const int t    = threadIdx.x;                 // 0..511
    const int lane = t & 31;
    const int w    = t >> 5;
    const int s0   = w * WPOS;
    const int rgrp = lane >> 3;                   // which of 4 rows
    const int vgrp = lane & 7;                    // 16B chunk within the row
    const signed char* __restrict__ bp = g_q;

    if (t < SEQ) {
        const int c = chars[b * SEQ + t];
        const bool act = (c > 0);
        offs[t] = (act ? (t * VOC + c - 1) : ZROW) * VPAD;
        const unsigned m = __ballot_sync(0xffffffffu, act);
        if (lane == 0) cnt8[w] = __popc(m);
    }
    __syncthreads();

    int acc[16];
    #pragma unroll
    for (int k = 0; k < 16; k++) acc[k] = 0;

    const int vb = vgrp * 16;
    const int4 x0 = __ldcg((const int4*)(bp + offs[s0      + rgrp] + vb));
    const int4 x1 = __ldcg((const int4*)(bp + offs[s0 +  4 + rgrp] + vb));
    const int4 x2 = __ldcg((const int4*)(bp + offs[s0 +  8 + rgrp] + vb));
    ACCUM(x0);
    const int4 x3 = __ldcg((const int4*)(bp + offs[s0 + 12 + rgrp] + vb));
    ACCUM(x1);
    ACCUM(x2);
    ACCUM(x3);

    if (vgrp < 6) {                               // lanes with real vocab data
        int4* dst = (int4*)&part[w][rgrp][vgrp][0];
        dst[0] = make_int4(acc[ 0], acc[ 1], acc[ 2], acc[ 3]);
        dst[1] = make_int4(acc[ 4], acc[ 5], acc[ 6], acc[ 7]);
        dst[2] = make_int4(acc[ 8], acc[ 9], acc[10], acc[11]);
        dst[3] = make_int4(acc[12], acc[13], acc[14], acc[15]);
    }
    __syncthreads();

    // Final reduce: thread v<96 sums its vocab entry over 16 warps x 4 rgrps.
    if (t < VOC) {
        const int vg  = t >> 4;                   // 0..5
        const int rem = t & 15;
        int s = 0;
        #pragma unroll
        for (int k = 0; k < NWARP; k++) {
            #pragma unroll
            for (int r = 0; r < 4; r++)
                s += part[k][r][vg][rem];
        }
        int nact = 0;
        #pragma unroll
        for (int k = 0; k < 8; k++) nact += cnt8[k];
        const float inv  = __frcp_rn((float)max(nact, 1));
        const float corr = 256.0f * QM - (float)(SEQ - nact) * EPSZ;
        out[b * VOC + t] = __expf((QS * (float)s + corr) * inv);
    }
}

// ---------------------------------------------------------------------------
extern "C" void kernel_launch(void* const* d_in, const int* in_sizes, int n_in,
                              void* d_out, int out_size) {
    const int*   chars = (const int*)d_in[0];     // (B, 256) int32
    const float* raw   = (const float*)d_in[1];   // (96, 24576) float32
    float*       out   = (float*)d_out;           // (B, 96) float32

    const int batch = in_sizes[0] / SEQ;

    dim3 pgrid(DEND / 32, VOC / 32);              // (768, 3)
    dim3 pblk(32, 8);
    prep_kernel<<<pgrid, pblk>>>(raw);

    gather_kernel<<<batch, 32 * NWARP>>>(chars, out);
}

// round 12
// speedup vs baseline: 1.1696x; 1.1518x over previous
#include <cuda_runtime.h>
#include <cuda_fp16.h>

#define SEQ    256
#define VOC    96
#define DEND   (SEQ * VOC)           // 24576 dendrites
#define ZROW   DEND                  // masked-position row (QZ codes)
#define NWARP  16
#define SPB    4                     // samples per block, ONE merged chain
#define WPOS   (SEQ / NWARP)         // 16 positions per warp per sample

// log_w range: [log(2*sig(-1)), log(2*sig(1))] = [-0.620115, 0.379885], width 1.0
#define QS    0.0039370079f          // 1/254
#define QINV  254.0f
#define QM    (-0.1201145f)          // range midpoint
#define EPSZ  0.0019327f             // residual of masked-row code (QZ=31)

// int8 quantized transposed table (96B rows): g_q[d*96+v]
__device__ __align__(128) signed char g_q[(DEND + 1) * VOC + 128];

// ---------------------------------------------------------------------------
// Kernel A: sigmoid/log + quantize + transpose. grid (768,3), block (32,8).
// ---------------------------------------------------------------------------
__global__ void prep_kernel(const float* __restrict__ raw) {
    __shared__ float tile[32][33];      // tile[v_local][d_local]
    const int d0 = blockIdx.x * 32;
    const int v0 = blockIdx.y * 32;
    const int tx = threadIdx.x, ty = threadIdx.y;

    #pragma unroll
    for (int i = ty; i < 32; i += 8) {
        const float x = raw[(v0 + i) * DEND + (d0 + tx)];
        tile[i][tx] = 0.69314718f - __logf(1.0f + __expf(-x));
    }
    __syncthreads();

    const int t  = ty * 32 + tx;        // 0..255
    const int dl = t >> 3;              // d_local 0..31
    const int vq = t & 7;               // which char4 of 32 v's

    char4 c;
    #pragma unroll
    for (int k = 0; k < 4; k++) {
        const float lw = tile[4 * vq + k][dl];
        int qi = __float2int_rn((lw - QM) * QINV);
        qi = max(-127, min(127, qi));
        ((char*)&c)[k] = (signed char)qi;
    }
    *(char4*)(g_q + (d0 + dl) * VOC + v0 + 4 * vq) = c;

    if (blockIdx.x == 0 && blockIdx.y == 0 && t < VOC / 4) {
        ((int*)(g_q + ZROW * VOC))[t] = 0x1F1F1F1F;   // QZ=31 per byte
    }
}

// dp4a extraction of one 32-bit word (4 vocab entries) into acc[s][0..3]
#define ACCS(W, s) do {                                                 \
    const int _w = (int)(W);                                            \
    acc[s][0] = __dp4a(_w, (int)0x00000001, acc[s][0]);                 \
    acc[s][1] = __dp4a(_w, (int)0x00000100, acc[s][1]);                 \
    acc[s][2] = __dp4a(_w, (int)0x00010000, acc[s][2]);                 \
    acc[s][3] = __dp4a(_w, (int)0x01000000, acc[s][3]);                 \
} while (0)

// ---------------------------------------------------------------------------
// Kernel B: FOUR samples per block in ONE merged chain. 512 threads.
// Warp w covers positions [16w,16w+16) of all 4 samples: 64 loads per
// thread with 4-way sample interleaving -> sustained MLP, amortized
// barriers/chars/reduce. Exact int32 dp4a accumulation (96B rows, R7 base).
// ---------------------------------------------------------------------------
__global__ void __launch_bounds__(32 * NWARP)
gather_kernel(const int* __restrict__ chars,
              float* __restrict__ out) {
    __shared__ int offs[SPB][SEQ];                // byte offsets of rows
    __shared__ int cnt[SPB][8];                   // per-warp active counts
    __shared__ int part[NWARP][SPB][24][4];       // 24 KB int partials

    const int b0   = blockIdx.x * SPB;
    const int t    = threadIdx.x;                 // 0..511
    const int lane = t & 31;
    const int w    = t >> 5;
    const int s0   = w * WPOS;
    const int al   = (lane < 24) ? lane : lane - 8;   // dup lanes share lines
    const int ll4  = al * 4;
    const signed char* __restrict__ bp = g_q;

    // Build offsets for all 4 samples (1024 chars, 2 per thread).
    #pragma unroll
    for (int r = 0; r < 2; r++) {
        const int i   = t + r * 512;              // 0..1023
        const int smp = i >> 8;
        const int s   = i & (SEQ - 1);
        const int c   = chars[(b0 + smp) * SEQ + s];
        const bool act = (c > 0);
        offs[smp][s] = (act ? (s * VOC + c - 1) : ZROW) * VOC;
        const unsigned m = __ballot_sync(0xffffffffu, act);
        if (lane == 0) cnt[smp][w & 7] = __popc(m);
    }
    __syncthreads();

    int acc[SPB][4];
    #pragma unroll
    for (int s = 0; s < SPB; s++) {
        acc[s][0] = 0; acc[s][1] = 0; acc[s][2] = 0; acc[s][3] = 0;
    }

    // Merged gather: per position, 4 independent loads (one per sample).
    #pragma unroll
    for (int i = 0; i < WPOS; i++) {
        const int x0 = __ldg((const int*)(bp + offs[0][s0 + i] + ll4));
        const int x1 = __ldg((const int*)(bp + offs[1][s0 + i] + ll4));
        const int x2 = __ldg((const int*)(bp + offs[2][s0 + i] + ll4));
        const int x3 = __ldg((const int*)(bp + offs[3][s0 + i] + ll4));
        ACCS(x0, 0);
        ACCS(x1, 1);
        ACCS(x2, 2);
        ACCS(x3, 3);
    }

    if (lane < 24) {
        #pragma unroll
        for (int s = 0; s < SPB; s++) {
            *(int4*)&part[w][s][al][0] =
                make_int4(acc[s][0], acc[s][1], acc[s][2], acc[s][3]);
        }
    }
    __syncthreads();

    // Reduce: 384 threads, thread -> (sample=t/96, vocab=t%96).
    if (t < SPB * VOC) {
        const int smp = t / VOC;
        const int v   = t - smp * VOC;
        int s = 0;
        #pragma unroll
        for (int k = 0; k < NWARP; k++)
            s += part[k][smp][v >> 2][v & 3];
        int nact = 0;
        #pragma unroll
        for (int k = 0; k < 8; k++) nact += cnt[smp][k];
        const float inv  = __frcp_rn((float)max(nact, 1));
        const float corr = 256.0f * QM - (float)(SEQ - nact) * EPSZ;
        out[b0 * VOC + t] = __expf((QS * (float)s + corr) * inv);
    }
}

// ---------------------------------------------------------------------------
extern "C" void kernel_launch(void* const* d_in, const int* in_sizes, int n_in,
                              void* d_out, int out_size) {
    const int*   chars = (const int*)d_in[0];     // (B, 256) int32
    const float* raw   = (const float*)d_in[1];   // (96, 24576) float32
    float*       out   = (float*)d_out;           // (B, 96) float32

    const int batch = in_sizes[0] / SEQ;

    dim3 pgrid(DEND / 32, VOC / 32);              // (768, 3)
    dim3 pblk(32, 8);
    prep_kernel<<<pgrid, pblk>>>(raw);

    gather_kernel<<<batch / SPB, 32 * NWARP>>>(chars, out);
}

// round 13
// speedup vs baseline: 1.2220x; 1.0448x over previous
#include <cuda_runtime.h>
#include <cuda_fp16.h>

#define SEQ    256
#define VOC    96
#define DEND   (SEQ * VOC)           // 24576 dendrites
#define ZROW   DEND                  // masked-position row (code 79)
#define NWARP  16
#define SPB    4                     // samples per block, one merged chain
#define WPOS   (SEQ / NWARP)         // 16 positions per warp per sample

// log_w = log(2*sigmoid(x)), x in (-1,1): range [LO, LO+1] exactly (width 1).
#define QLO   (-0.62011451f)         // log(2/(1+e))
#define QS7   (1.0f / 127.0f)        // 7-bit step
#define QZ7   79                     // masked-row code: round(0.620115*127)
#define EPSZ  0.00193274f            // 79/127 + QLO (masked-row residual)

// 7-bit unsigned quantized transposed table (96B rows): g_q[d*96+v]
__device__ __align__(128) unsigned char g_q[(DEND + 1) * VOC + 128];

// ---------------------------------------------------------------------------
// Kernel A: sigmoid/log + 7-bit quantize + transpose. grid (768,3), block (32,8).
// ---------------------------------------------------------------------------
__global__ void prep_kernel(const float* __restrict__ raw) {
    __shared__ float tile[32][33];      // tile[v_local][d_local]
    const int d0 = blockIdx.x * 32;
    const int v0 = blockIdx.y * 32;
    const int tx = threadIdx.x, ty = threadIdx.y;

    #pragma unroll
    for (int i = ty; i < 32; i += 8) {
        const float x = raw[(v0 + i) * DEND + (d0 + tx)];
        tile[i][tx] = 0.69314718f - __logf(1.0f + __expf(-x));
    }
    __syncthreads();

    const int t  = ty * 32 + tx;        // 0..255
    const int dl = t >> 3;              // d_local 0..31
    const int vq = t & 7;               // which uchar4 of 32 v's

    uchar4 c;
    #pragma unroll
    for (int k = 0; k < 4; k++) {
        const float lw = tile[4 * vq + k][dl];
        int qi = __float2int_rn((lw - QLO) * 127.0f);
        qi = max(0, min(127, qi));
        ((unsigned char*)&c)[k] = (unsigned char)qi;
    }
    *(uchar4*)(g_q + (d0 + dl) * VOC + v0 + 4 * vq) = c;

    if (blockIdx.x == 0 && blockIdx.y == 0 && t < VOC / 4) {
        ((unsigned*)(g_q + ZROW * VOC))[t] = 0x4F4F4F4Fu;   // code 79 per byte
    }
}

// ---------------------------------------------------------------------------
// Kernel B: FOUR samples per block, one merged chain, 512 threads.
// 7-bit codes: two packed rows sum with ONE carry-free IADD, then 4 dp4a
// extract per PAIR of positions -> ~1.6 instr per vocab entry (was 2.25).
// ---------------------------------------------------------------------------
__global__ void __launch_bounds__(32 * NWARP)
gather_kernel(const int* __restrict__ chars,
              float* __restrict__ out) {
    __shared__ int      offs[SPB][SEQ];           // byte offsets of rows
    __shared__ int      cnt[SPB][8];              // per-warp active counts
    __shared__ unsigned part[NWARP][SPB][24][4];  // 24 KB partials

    const int b0   = blockIdx.x * SPB;
    const int t    = threadIdx.x;                 // 0..511
    const int lane = t & 31;
    const int w    = t >> 5;
    const int s0   = w * WPOS;
    const int al   = (lane < 24) ? lane : lane - 8;   // dup lanes share lines
    const int ll4  = al * 4;
    const unsigned char* __restrict__ bp = g_q;

    // Offsets for all 4 samples (1024 chars, 2 per thread).
    #pragma unroll
    for (int r = 0; r < 2; r++) {
        const int i   = t + r * 512;              // 0..1023
        const int smp = i >> 8;
        const int s   = i & (SEQ - 1);
        const int c   = chars[(b0 + smp) * SEQ + s];
        const bool act = (c > 0);
        offs[smp][s] = (act ? (s * VOC + c - 1) : ZROW) * VOC;
        const unsigned m = __ballot_sync(0xffffffffu, act);
        if (lane == 0) cnt[smp][w & 7] = __popc(m);
    }
    __syncthreads();

    unsigned acc[SPB][4];
    #pragma unroll
    for (int s = 0; s < SPB; s++) {
        acc[s][0] = 0u; acc[s][1] = 0u; acc[s][2] = 0u; acc[s][3] = 0u;
    }

    // Merged gather: 8 pair-iterations x 4 samples = 8 independent loads
    // per iteration; 1 IADD + 4 dp4a per pair (carry-free 7-bit sum).
    #pragma unroll
    for (int i = 0; i < WPOS; i += 2) {
        #pragma unroll
        for (int s = 0; s < SPB; s++) {
            const unsigned xa = *(const unsigned*)(bp + offs[s][s0 + i]     + ll4);
            const unsigned xb = *(const unsigned*)(bp + offs[s][s0 + i + 1] + ll4);
            const unsigned y  = xa + xb;          // exact per-byte sums (<=254)
            acc[s][0] = __dp4a(y, 0x00000001u, acc[s][0]);
            acc[s][1] = __dp4a(y, 0x00000100u, acc[s][1]);
            acc[s][2] = __dp4a(y, 0x00010000u, acc[s][2]);
            acc[s][3] = __dp4a(y, 0x01000000u, acc[s][3]);
        }
    }

    if (lane < 24) {
        #pragma unroll
        for (int s = 0; s < SPB; s++) {
            *(uint4*)&part[w][s][al][0] =
                make_uint4(acc[s][0], acc[s][1], acc[s][2], acc[s][3]);
        }
    }
    __syncthreads();

    // Reduce: 384 threads, thread -> (sample=t/96, vocab=t%96).
    if (t < SPB * VOC) {
        const int smp = t / VOC;
        const int v   = t - smp * VOC;
        unsigned s = 0;
        #pragma unroll
        for (int k = 0; k < NWARP; k++)
            s += part[k][smp][v >> 2][v & 3];
        int nact = 0;
        #pragma unroll
        for (int k = 0; k < 8; k++) nact += cnt[smp][k];
        const float inv  = __frcp_rn((float)max(nact, 1));
        // log_sum = QS7*sum(q) + 256*QLO - n_masked*EPSZ
        const float corr = 256.0f * QLO - (float)(SEQ - nact) * EPSZ;
        out[b0 * VOC + t] = __expf((QS7 * (float)s + corr) * inv);
    }
}

// ---------------------------------------------------------------------------
extern "C" void kernel_launch(void* const* d_in, const int* in_sizes, int n_in,
                              void* d_out, int out_size) {
    const int*   chars = (const int*)d_in[0];     // (B, 256) int32
    const float* raw   = (const float*)d_in[1];   // (96, 24576) float32
    float*       out   = (float*)d_out;           // (B, 96) float32

    const int batch = in_sizes[0] / SEQ;

    dim3 pgrid(DEND / 32, VOC / 32);              // (768, 3)
    dim3 pblk(32, 8);
    prep_kernel<<<pgrid, pblk>>>(raw);

    gather_kernel<<<batch / SPB, 32 * NWARP>>>(chars, out);
}

// round 14
// speedup vs baseline: 1.2429x; 1.0171x over previous
#include <cuda_runtime.h>
#include <cuda_fp16.h>

#define SEQ    256
#define VOC    96
#define DEND   (SEQ * VOC)           // 24576 dendrites
#define ZROW   DEND                  // masked-position row (code 79)
#define NWARP  16
#define SPB    4                     // samples per block, one merged chain
#define WPOS   (SEQ / NWARP)         // 16 positions per warp per sample

// log_w = log(2*sigmoid(x)), x in (-1,1): range [LO, LO+1] exactly (width 1).
#define QLO   (-0.62011451f)         // log(2/(1+e))
#define QS7   (1.0f / 127.0f)        // 7-bit step
#define EPSZ  0.00193274f            // 79/127 + QLO (masked-row residual)

// 7-bit unsigned quantized transposed table (96B rows): g_q[d*96+v]
__device__ __align__(128) unsigned char g_q[(DEND + 1) * VOC + 128];

// ---------------------------------------------------------------------------
// Kernel A: sigmoid/log + 7-bit quantize + transpose. grid (768,3), block (32,8).
// ---------------------------------------------------------------------------
__global__ void prep_kernel(const float* __restrict__ raw) {
    __shared__ float tile[32][33];      // tile[v_local][d_local]
    const int d0 = blockIdx.x * 32;
    const int v0 = blockIdx.y * 32;
    const int tx = threadIdx.x, ty = threadIdx.y;

    #pragma unroll
    for (int i = ty; i < 32; i += 8) {
        const float x = raw[(v0 + i) * DEND + (d0 + tx)];
        tile[i][tx] = 0.69314718f - __logf(1.0f + __expf(-x));
    }
    __syncthreads();

    const int t  = ty * 32 + tx;        // 0..255
    const int dl = t >> 3;              // d_local 0..31
    const int vq = t & 7;               // which uchar4 of 32 v's

    uchar4 c;
    #pragma unroll
    for (int k = 0; k < 4; k++) {
        const float lw = tile[4 * vq + k][dl];
        int qi = __float2int_rn((lw - QLO) * 127.0f);
        qi = max(0, min(127, qi));
        ((unsigned char*)&c)[k] = (unsigned char)qi;
    }
    *(uchar4*)(g_q + (d0 + dl) * VOC + v0 + 4 * vq) = c;

    if (blockIdx.x == 0 && blockIdx.y == 0 && t < VOC / 4) {
        ((unsigned*)(g_q + ZROW * VOC))[t] = 0x4F4F4F4Fu;   // code 79 per byte
    }
}

// ---------------------------------------------------------------------------
// Kernel B: FOUR samples per block, one merged chain, 512 threads,
// FOUR blocks per SM (reg-capped). Offsets fetched via LDS.128 broadcast
// (4 positions at once); carry-free 7-bit pair sums halve dp4a extraction.
// ---------------------------------------------------------------------------
__global__ void __launch_bounds__(32 * NWARP, 4)
gather_kernel(const int* __restrict__ chars,
              float* __restrict__ out) {
    __shared__ __align__(16) int offs[SPB][SEQ];  // byte offsets of rows
    __shared__ int      cnt[SPB][8];              // per-warp active counts
    __shared__ unsigned part[NWARP][SPB][24][4];  // 24 KB partials

    const int b0   = blockIdx.x * SPB;
    const int t    = threadIdx.x;                 // 0..511
    const int lane = t & 31;
    const int w    = t >> 5;
    const int s0   = w * WPOS;
    const int al   = (lane < 24) ? lane : lane - 8;   // dup lanes share lines
    const unsigned char* __restrict__ bp = g_q + al * 4;

    // Offsets for all 4 samples (1024 chars, 2 per thread).
    #pragma unroll
    for (int r = 0; r < 2; r++) {
        const int i   = t + r * 512;              // 0..1023
        const int smp = i >> 8;
        const int s   = i & (SEQ - 1);
        const int c   = chars[(b0 + smp) * SEQ + s];
        const bool act = (c > 0);
        offs[smp][s] = (act ? (s * VOC + c - 1) : ZROW) * VOC;
        const unsigned m = __ballot_sync(0xffffffffu, act);
        if (lane == 0) cnt[smp][w & 7] = __popc(m);
    }
    __syncthreads();

    unsigned acc[SPB][4];
    #pragma unroll
    for (int s = 0; s < SPB; s++) {
        acc[s][0] = 0u; acc[s][1] = 0u; acc[s][2] = 0u; acc[s][3] = 0u;
    }

    // 4 group-iterations; per group x sample: 1 LDS.128 (4 offsets),
    // 4 LDG.32, 2 carry-free IADDs, 8 dp4a.
    #pragma unroll
    for (int g = 0; g < WPOS; g += 4) {
        #pragma unroll
        for (int s = 0; s < SPB; s++) {
            const int4 o = *(const int4*)&offs[s][s0 + g];
            const unsigned xa = *(const unsigned*)(bp + o.x);
            const unsigned xb = *(const unsigned*)(bp + o.y);
            const unsigned xc = *(const unsigned*)(bp + o.z);
            const unsigned xd = *(const unsigned*)(bp + o.w);
            const unsigned y0 = xa + xb;          // per-byte sums <= 254
            const unsigned y1 = xc + xd;
            acc[s][0] = __dp4a(y0, 0x00000001u, acc[s][0]);
            acc[s][1] = __dp4a(y0, 0x00000100u, acc[s][1]);
            acc[s][2] = __dp4a(y0, 0x00010000u, acc[s][2]);
            acc[s][3] = __dp4a(y0, 0x01000000u, acc[s][3]);
            acc[s][0] = __dp4a(y1, 0x00000001u, acc[s][0]);
            acc[s][1] = __dp4a(y1, 0x00000100u, acc[s][1]);
            acc[s][2] = __dp4a(y1, 0x00010000u, acc[s][2]);
            acc[s][3] = __dp4a(y1, 0x01000000u, acc[s][3]);
        }
    }

    if (lane < 24) {
        #pragma unroll
        for (int s = 0; s < SPB; s++) {
            *(uint4*)&part[w][s][al][0] =
                make_uint4(acc[s][0], acc[s][1], acc[s][2], acc[s][3]);
        }
    }
    __syncthreads();

    // Reduce: 384 threads, thread -> (sample=t/96, vocab=t%96).
    if (t < SPB * VOC) {
        const int smp = t / VOC;
        const int v   = t - smp * VOC;
        unsigned s = 0;
        #pragma unroll
        for (int k = 0; k < NWARP; k++)
            s += part[k][smp][v >> 2][v & 3];
        int nact = 0;
        #pragma unroll
        for (int k = 0; k < 8; k++) nact += cnt[smp][k];
        const float inv  = __frcp_rn((float)max(nact, 1));
        const float corr = 256.0f * QLO - (float)(SEQ - nact) * EPSZ;
        out[b0 * VOC + t] = __expf((QS7 * (float)s + corr) * inv);
    }
}

// ---------------------------------------------------------------------------
extern "C" void kernel_launch(void* const* d_in, const int* in_sizes, int n_in,
                              void* d_out, int out_size) {
    const int*   chars = (const int*)d_in[0];     // (B, 256) int32
    const float* raw   = (const float*)d_in[1];   // (96, 24576) float32
    float*       out   = (float*)d_out;           // (B, 96) float32

    const int batch = in_sizes[0] / SEQ;

    dim3 pgrid(DEND / 32, VOC / 32);              // (768, 3)
    dim3 pblk(32, 8);
    prep_kernel<<<pgrid, pblk>>>(raw);

    gather_kernel<<<batch / SPB, 32 * NWARP>>>(chars, out);
}